// round 1
// baseline (speedup 1.0000x reference)
#include <cuda_runtime.h>
#include <math.h>

// Problem constants (from reference)
#define NN 100000
#define EE 1600000
#define GG 1024

// ---------------- scratch (__device__ globals; no allocations) ----------------
__device__ float    g_h1  [NN * 128];   // layer1 transformed features [N,4,32]
__device__ float    g_es1 [NN * 4];     // per-node src attention logits
__device__ float    g_ed1 [NN * 4];     // per-node dst attention logits
__device__ unsigned g_m1  [NN * 4];     // encoded segment max
__device__ float    g_den1[NN * 4];     // softmax denominators
__device__ float    g_out1[NN * 128];   // unnormalized aggregated messages
__device__ float    g_h2  [NN * 32];
__device__ float    g_es2 [NN];
__device__ float    g_ed2 [NN];
__device__ unsigned g_m2  [NN];
__device__ float    g_den2[NN];
__device__ float    g_out2[NN * 32];
__device__ float    g_msum[GG * 32];    // mean-pool accumulator
__device__ unsigned g_mmax[GG * 32];    // encoded max-pool
__device__ float    g_cnt [GG];

// ---------------- helpers ----------------
__device__ __forceinline__ unsigned fenc(float f) {
    unsigned u = __float_as_uint(f);
    return (u & 0x80000000u) ? ~u : (u | 0x80000000u);
}
__device__ __forceinline__ float fdec(unsigned u) {
    return __uint_as_float((u & 0x80000000u) ? (u & 0x7FFFFFFFu) : ~u);
}
__device__ __forceinline__ float lrelu(float v) { return v > 0.f ? v : 0.2f * v; }
__device__ __forceinline__ float elu(float v)   { return v > 0.f ? v : expf(v) - 1.f; }

// ---------------- K1: h1 = x @ W1, per-node attention logits ----------------
__global__ void k_h1(const float* __restrict__ x, const float* __restrict__ W1,
                     const float* __restrict__ as1, const float* __restrict__ ad1, int N) {
    __shared__ float sW[7 * 128];
    __shared__ float ss[128], sd[128];
    int t = threadIdx.x;  // 128 threads
    for (int i = t; i < 896; i += 128) sW[i] = W1[i];
    ss[t] = as1[t]; sd[t] = ad1[t];
    __syncthreads();
    int head = t >> 5;
    int n0 = blockIdx.x * 8, n1 = min(n0 + 8, N);
    for (int n = n0; n < n1; n++) {
        float h = 0.f;
        #pragma unroll
        for (int k = 0; k < 7; k++) h += x[n * 7 + k] * sW[k * 128 + t];
        g_h1[n * 128 + t] = h;
        float es = h * ss[t], ed = h * sd[t];
        #pragma unroll
        for (int o = 16; o; o >>= 1) {
            es += __shfl_down_sync(0xFFFFFFFFu, es, o);
            ed += __shfl_down_sync(0xFFFFFFFFu, ed, o);
        }
        if ((t & 31) == 0) { g_es1[n * 4 + head] = es; g_ed1[n * 4 + head] = ed; }
    }
}

// ---------------- K2: init segment max with self-loop score ----------------
__global__ void k_m1_init(int N) {
    int i = blockIdx.x * blockDim.x + threadIdx.x;
    if (i >= N * 4) return;
    g_m1[i] = fenc(lrelu(g_es1[i] + g_ed1[i]));
}

// ---------------- K3: edge max (layer1) ----------------
__global__ void k_m1_edge(const int* __restrict__ src, const int* __restrict__ dst, int E) {
    int e = blockIdx.x * blockDim.x + threadIdx.x;
    if (e >= E) return;
    int s = src[e], d = dst[e];
    const float4 es = *(const float4*)&g_es1[s * 4];
    const float4 ed = *(const float4*)&g_ed1[d * 4];
    unsigned* m = &g_m1[d * 4];
    atomicMax(m + 0, fenc(lrelu(es.x + ed.x)));
    atomicMax(m + 1, fenc(lrelu(es.y + ed.y)));
    atomicMax(m + 2, fenc(lrelu(es.z + ed.z)));
    atomicMax(m + 3, fenc(lrelu(es.w + ed.w)));
}

// ---------------- K4: self-loop contribution seeds denom + out ----------------
__global__ void k_self1(int N) {
    int i = blockIdx.x * blockDim.x + threadIdx.x;
    if (i >= N * 128) return;
    int n = i >> 7, t = i & 127, h = t >> 5;
    float eself = lrelu(g_es1[n * 4 + h] + g_ed1[n * 4 + h]);
    float p = expf(eself - fdec(g_m1[n * 4 + h]));
    if ((t & 31) == 0) g_den1[n * 4 + h] = p;
    g_out1[i] = p * g_h1[i];
}

// ---------------- K5: fused exp-sum + message aggregation (layer1) ----------------
// One warp per edge: 32 lanes x float4 = 128 floats.
__global__ void k_agg1(const int* __restrict__ src, const int* __restrict__ dst, int E) {
    int gid = blockIdx.x * blockDim.x + threadIdx.x;
    int e = gid >> 5, lane = gid & 31;
    if (e >= E) return;
    int s = src[e], d = dst[e];
    const float4 es = *(const float4*)&g_es1[s * 4];
    const float4 ed = *(const float4*)&g_ed1[d * 4];
    const uint4  mu = *(const uint4*)&g_m1[d * 4];
    float p0 = expf(lrelu(es.x + ed.x) - fdec(mu.x));
    float p1 = expf(lrelu(es.y + ed.y) - fdec(mu.y));
    float p2 = expf(lrelu(es.z + ed.z) - fdec(mu.z));
    float p3 = expf(lrelu(es.w + ed.w) - fdec(mu.w));
    if (lane == 0) atomicAdd((float4*)&g_den1[d * 4], make_float4(p0, p1, p2, p3));
    int hh = lane >> 3;  // head for this float4 (32 floats per head)
    float ph = hh == 0 ? p0 : hh == 1 ? p1 : hh == 2 ? p2 : p3;
    float4 hv = *(const float4*)&g_h1[s * 128 + lane * 4];
    float4 mv = make_float4(hv.x * ph, hv.y * ph, hv.z * ph, hv.w * ph);
    atomicAdd((float4*)&g_out1[d * 128 + lane * 4], mv);
}

// ---------------- K6: normalize + bias + ELU, then h2 = act1 @ W2 + logits ----------------
__global__ void k_layer2_prep(const float* __restrict__ b1, const float* __restrict__ W2,
                              const float* __restrict__ as2, const float* __restrict__ ad2, int N) {
    __shared__ float sW2[128 * 32];
    __shared__ float sb1[128];
    __shared__ float sas[32], sad[32];
    __shared__ float srow[128];
    __shared__ float spart[128];
    int t = threadIdx.x;  // 128
    for (int i = t; i < 4096; i += 128) sW2[i] = W2[i];
    sb1[t] = b1[t];
    if (t < 32) { sas[t] = as2[t]; sad[t] = ad2[t]; }
    __syncthreads();
    int head = t >> 5;
    int n0 = blockIdx.x * 16, n1 = min(n0 + 16, N);
    for (int n = n0; n < n1; n++) {
        float den = g_den1[n * 4 + head] + 1e-16f;
        float v = elu(g_out1[n * 128 + t] / den + sb1[t]);
        srow[t] = v;
        __syncthreads();
        int c = t & 31, kq = t >> 5;
        float acc = 0.f;
        #pragma unroll
        for (int k = 0; k < 32; k++) acc += srow[kq * 32 + k] * sW2[(kq * 32 + k) * 32 + c];
        spart[t] = acc;
        __syncthreads();
        if (t < 32) {
            float h2 = spart[t] + spart[32 + t] + spart[64 + t] + spart[96 + t];
            g_h2[n * 32 + t] = h2;
            float es = h2 * sas[t], ed = h2 * sad[t];
            #pragma unroll
            for (int o = 16; o; o >>= 1) {
                es += __shfl_down_sync(0xFFFFFFFFu, es, o);
                ed += __shfl_down_sync(0xFFFFFFFFu, ed, o);
            }
            if (t == 0) { g_es2[n] = es; g_ed2[n] = ed; }
        }
        __syncthreads();
    }
}

// ---------------- K7: init layer2 segment max with self loop ----------------
__global__ void k_m2_init(int N) {
    int n = blockIdx.x * blockDim.x + threadIdx.x;
    if (n >= N) return;
    g_m2[n] = fenc(lrelu(g_es2[n] + g_ed2[n]));
}

// ---------------- K8: edge max (layer2) ----------------
__global__ void k_m2_edge(const int* __restrict__ src, const int* __restrict__ dst, int E) {
    int e = blockIdx.x * blockDim.x + threadIdx.x;
    if (e >= E) return;
    int s = src[e], d = dst[e];
    atomicMax(&g_m2[d], fenc(lrelu(g_es2[s] + g_ed2[d])));
}

// ---------------- K9: self-loop seed (layer2) ----------------
__global__ void k_self2(int N) {
    int i = blockIdx.x * blockDim.x + threadIdx.x;
    if (i >= N * 32) return;
    int n = i >> 5, c = i & 31;
    float p = expf(lrelu(g_es2[n] + g_ed2[n]) - fdec(g_m2[n]));
    if (c == 0) g_den2[n] = p;
    g_out2[i] = p * g_h2[i];
}

// ---------------- K10: fused exp-sum + aggregation (layer2), 8 lanes/edge ----------------
__global__ void k_agg2(const int* __restrict__ src, const int* __restrict__ dst, int E) {
    int gid = blockIdx.x * blockDim.x + threadIdx.x;
    int e = gid >> 3, li = gid & 7;
    if (e >= E) return;
    int s = src[e], d = dst[e];
    float p = expf(lrelu(g_es2[s] + g_ed2[d]) - fdec(g_m2[d]));
    if (li == 0) atomicAdd(&g_den2[d], p);
    float4 hv = *(const float4*)&g_h2[s * 32 + li * 4];
    float4 mv = make_float4(hv.x * p, hv.y * p, hv.z * p, hv.w * p);
    atomicAdd((float4*)&g_out2[d * 32 + li * 4], mv);
}

// ---------------- K11: init pools ----------------
__global__ void k_pool_init() {
    int i = blockIdx.x * blockDim.x + threadIdx.x;
    if (i < GG * 32) { g_msum[i] = 0.f; g_mmax[i] = 0u; }
    if (i < GG) g_cnt[i] = 0.f;
}

// ---------------- K12: finalize layer2 act, accumulate graph pools ----------------
__global__ void k_pool(const float* __restrict__ b2, const int* __restrict__ batch, int N) {
    int gid = blockIdx.x * blockDim.x + threadIdx.x;
    int n = gid >> 5, c = gid & 31;
    if (n >= N) return;
    float v = elu(g_out2[n * 32 + c] / (g_den2[n] + 1e-16f) + b2[c]);
    int g = batch[n];
    atomicAdd(&g_msum[g * 32 + c], v);
    atomicMax(&g_mmax[g * 32 + c], fenc(v));
    if (c == 0) atomicAdd(&g_cnt[g], 1.f);
}

// ---------------- K13: readout MLP ----------------
__global__ void k_mlp(const float* __restrict__ Wm1, const float* __restrict__ bm1,
                      const float* __restrict__ Wm2, const float* __restrict__ bm2,
                      float* __restrict__ out) {
    __shared__ float gv[64];
    __shared__ float red[64];
    int g = blockIdx.x, j = threadIdx.x;  // 64 threads
    if (j < 32) gv[j] = g_msum[g * 32 + j] / g_cnt[g];
    else        gv[j] = fdec(g_mmax[g * 32 + (j - 32)]);
    __syncthreads();
    float acc = bm1[j];
    #pragma unroll 8
    for (int i = 0; i < 64; i++) acc += gv[i] * Wm1[i * 64 + j];
    red[j] = fmaxf(acc, 0.f) * Wm2[j];
    __syncthreads();
    // tree reduce 64 -> 1
    for (int o = 32; o; o >>= 1) {
        if (j < o) red[j] += red[j + o];
        __syncthreads();
    }
    if (j == 0) out[g] = red[0] + bm2[0];
}

// ---------------- host ----------------
extern "C" void kernel_launch(void* const* d_in, const int* in_sizes, int n_in,
                              void* d_out, int out_size) {
    const float* x    = (const float*)d_in[0];
    const int*   ei   = (const int*)  d_in[1];
    const int*   bat  = (const int*)  d_in[2];
    const float* W1   = (const float*)d_in[3];
    const float* as1  = (const float*)d_in[4];
    const float* ad1  = (const float*)d_in[5];
    const float* b1   = (const float*)d_in[6];
    const float* W2   = (const float*)d_in[7];
    const float* as2  = (const float*)d_in[8];
    const float* ad2  = (const float*)d_in[9];
    const float* b2   = (const float*)d_in[10];
    const float* Wm1  = (const float*)d_in[11];
    const float* bm1  = (const float*)d_in[12];
    const float* Wm2  = (const float*)d_in[13];
    const float* bm2  = (const float*)d_in[14];
    float* out = (float*)d_out;

    int N = in_sizes[0] / 7;
    int E = in_sizes[1] / 2;
    const int* src = ei;
    const int* dst = ei + E;

    // Layer 1
    k_h1<<<(N + 7) / 8, 128>>>(x, W1, as1, ad1, N);
    k_m1_init<<<(N * 4 + 255) / 256, 256>>>(N);
    k_m1_edge<<<(E + 255) / 256, 256>>>(src, dst, E);
    k_self1<<<(N * 128 + 255) / 256, 256>>>(N);
    {
        long long thr = (long long)E * 32;
        k_agg1<<<(int)((thr + 255) / 256), 256>>>(src, dst, E);
    }
    // Layer 2 prep (normalize+ELU, matmul, logits)
    k_layer2_prep<<<(N + 15) / 16, 128>>>(b1, W2, as2, ad2, N);
    // Layer 2
    k_m2_init<<<(N + 255) / 256, 256>>>(N);
    k_m2_edge<<<(E + 255) / 256, 256>>>(src, dst, E);
    k_self2<<<(N * 32 + 255) / 256, 256>>>(N);
    {
        long long thr = (long long)E * 8;
        k_agg2<<<(int)((thr + 255) / 256), 256>>>(src, dst, E);
    }
    // Readout
    k_pool_init<<<(GG * 32 + 255) / 256, 256>>>();
    {
        long long thr = (long long)N * 32;
        k_pool<<<(int)((thr + 255) / 256), 256>>>(b2, bat, N);
    }
    k_mlp<<<GG, 64>>>(Wm1, bm1, Wm2, bm2, out);
}

// round 3
// speedup vs baseline: 2.1377x; 2.1377x over previous
#include <cuda_runtime.h>
#include <math.h>

#define NN 100000
#define EE 1700000
#define GG 1024

// ---------------- scratch ----------------
__device__ float    g_va_src[28];       // [i*4+h] = W1[:,h,:] @ a_src[h]
__device__ float    g_va_dst[28];
__device__ float    g_es1 [NN * 4];
__device__ float    g_ed1 [NN * 4];
__device__ float    g_acc [NN * 32];    // per-dst: [h*7+i]=Σ p*x_i ; [28+h]=Σ p
__device__ float    g_h2  [NN * 32];
__device__ float    g_es2 [NN];
__device__ float    g_ed2 [NN];
__device__ float    g_den2[NN];
__device__ float    g_out2[NN * 32];
__device__ float    g_msum[GG * 32];
__device__ unsigned g_mmax[GG * 32];
__device__ float    g_cnt [GG];

// ---------------- helpers ----------------
__device__ __forceinline__ unsigned fenc(float f) {
    unsigned u = __float_as_uint(f);
    return (u & 0x80000000u) ? ~u : (u | 0x80000000u);
}
__device__ __forceinline__ float fdec(unsigned u) {
    return __uint_as_float((u & 0x80000000u) ? (u & 0x7FFFFFFFu) : ~u);
}
__device__ __forceinline__ float lrelu(float v) { return v > 0.f ? v : 0.2f * v; }
__device__ __forceinline__ float elu(float v)   { return v > 0.f ? v : expf(v) - 1.f; }

// ---------------- K0: va = W1 @ a (7x4 each) ----------------
__global__ void k_va(const float* __restrict__ W1, const float* __restrict__ as1,
                     const float* __restrict__ ad1) {
    int t = threadIdx.x;  // 32
    if (t < 28) {
        int i = t >> 2, h = t & 3;
        float ss = 0.f, dd = 0.f;
        #pragma unroll
        for (int c = 0; c < 32; c++) {
            float w = W1[i * 128 + h * 32 + c];
            ss += w * as1[h * 32 + c];
            dd += w * ad1[h * 32 + c];
        }
        g_va_src[i * 4 + h] = ss;
        g_va_dst[i * 4 + h] = dd;
    }
}

// ---------------- K1: per-node logits + self-loop-seeded accumulator ----------------
__global__ void k_node1(const float* __restrict__ x, int N) {
    int n = blockIdx.x * blockDim.x + threadIdx.x;
    if (n >= N) return;
    float xv[7];
    #pragma unroll
    for (int i = 0; i < 7; i++) xv[i] = x[n * 7 + i];
    float es[4], ed[4];
    #pragma unroll
    for (int h = 0; h < 4; h++) {
        float s = 0.f, d = 0.f;
        #pragma unroll
        for (int i = 0; i < 7; i++) {
            s += xv[i] * g_va_src[i * 4 + h];
            d += xv[i] * g_va_dst[i * 4 + h];
        }
        es[h] = s; ed[h] = d;
    }
    *(float4*)&g_es1[n * 4] = make_float4(es[0], es[1], es[2], es[3]);
    *(float4*)&g_ed1[n * 4] = make_float4(ed[0], ed[1], ed[2], ed[3]);
    float p[4];
    #pragma unroll
    for (int h = 0; h < 4; h++) p[h] = expf(lrelu(es[h] + ed[h]));
    float a[32];
    #pragma unroll
    for (int h = 0; h < 4; h++) {
        #pragma unroll
        for (int i = 0; i < 7; i++) a[h * 7 + i] = p[h] * xv[i];
        a[28 + h] = p[h];
    }
    #pragma unroll
    for (int q = 0; q < 8; q++)
        *(float4*)&g_acc[n * 32 + q * 4] = make_float4(a[q*4], a[q*4+1], a[q*4+2], a[q*4+3]);
}

// ---------------- K2: layer1 edge aggregation (8 lanes/edge, 32 floats) ----------------
__global__ void k_agg1(const float* __restrict__ x, const int* __restrict__ src,
                       const int* __restrict__ dst, int E) {
    int gid = blockIdx.x * blockDim.x + threadIdx.x;
    int e = gid >> 3, lane = gid & 7;
    if (e >= E) return;
    int s = src[e], d = dst[e];
    const float4 es = *(const float4*)&g_es1[s * 4];
    const float4 ed = *(const float4*)&g_ed1[d * 4];
    float p[4];
    p[0] = expf(lrelu(es.x + ed.x));
    p[1] = expf(lrelu(es.y + ed.y));
    p[2] = expf(lrelu(es.z + ed.z));
    p[3] = expf(lrelu(es.w + ed.w));
    const float* xs = &x[s * 7];
    float v[4];
    // layout: idx in [0,28) -> p[idx/7]*x[idx%7]; idx in [28,32) -> p[idx-28]
    #pragma unroll
    for (int j = 0; j < 4; j++) {
        int idx = lane * 4 + j;
        int h7 = (idx * 9363) >> 16;        // idx/7 for idx<32 (magic div, exact)
        int i7 = idx - h7 * 7;
        v[j] = (idx < 28) ? p[h7] * __ldg(&xs[i7]) : p[idx - 28];
    }
    atomicAdd((float4*)&g_acc[d * 32 + lane * 4], make_float4(v[0], v[1], v[2], v[3]));
}

// ---------------- K3: acc -> act1 -> h2, layer2 logits (fused) ----------------
__global__ void k_finish1(const float* __restrict__ W1, const float* __restrict__ b1,
                          const float* __restrict__ W2, const float* __restrict__ as2,
                          const float* __restrict__ ad2, int N) {
    __shared__ float sW1[896];
    __shared__ float sb1[128];
    __shared__ float sW2[4096];
    __shared__ float sas[32], sad[32];
    __shared__ float sacc[32];
    __shared__ float sact[128];
    __shared__ float spart[128];
    int t = threadIdx.x;  // 128
    for (int i = t; i < 896; i += 128) sW1[i] = W1[i];
    sb1[t] = b1[t];
    for (int i = t; i < 4096; i += 128) sW2[i] = W2[i];
    if (t < 32) { sas[t] = as2[t]; sad[t] = ad2[t]; }
    __syncthreads();
    int h = t >> 5;
    int n0 = blockIdx.x * 16, n1 = min(n0 + 16, N);
    for (int n = n0; n < n1; n++) {
        if (t < 32) sacc[t] = g_acc[n * 32 + t];
        __syncthreads();
        float den = sacc[28 + h] + 1e-16f;
        float sum = 0.f;
        #pragma unroll
        for (int i = 0; i < 7; i++) sum += sacc[h * 7 + i] * sW1[i * 128 + t];
        float a = elu(sum / den + sb1[t]);
        sact[t] = a;
        __syncthreads();
        int c = t & 31, kq = t >> 5;
        float acc2 = 0.f;
        #pragma unroll
        for (int k = 0; k < 32; k++) acc2 += sact[kq * 32 + k] * sW2[(kq * 32 + k) * 32 + c];
        spart[t] = acc2;
        __syncthreads();
        if (t < 32) {
            float h2 = spart[t] + spart[32 + t] + spart[64 + t] + spart[96 + t];
            g_h2[n * 32 + t] = h2;
            float e_s = h2 * sas[t], e_d = h2 * sad[t];
            #pragma unroll
            for (int o = 16; o; o >>= 1) {
                e_s += __shfl_down_sync(0xFFFFFFFFu, e_s, o);
                e_d += __shfl_down_sync(0xFFFFFFFFu, e_d, o);
            }
            if (t == 0) { g_es2[n] = e_s; g_ed2[n] = e_d; }
        }
        __syncthreads();
    }
}

// ---------------- K4: self-loop seed (layer2) ----------------
__global__ void k_self2(int N) {
    int i = blockIdx.x * blockDim.x + threadIdx.x;
    if (i >= N * 32) return;
    int n = i >> 5, c = i & 31;
    float p = expf(lrelu(g_es2[n] + g_ed2[n]));
    if (c == 0) g_den2[n] = p;
    g_out2[i] = p * g_h2[i];
}

// ---------------- K5: layer2 edge aggregation (8 lanes/edge) ----------------
__global__ void k_agg2(const int* __restrict__ src, const int* __restrict__ dst, int E) {
    int gid = blockIdx.x * blockDim.x + threadIdx.x;
    int e = gid >> 3, li = gid & 7;
    if (e >= E) return;
    int s = src[e], d = dst[e];
    float p = expf(lrelu(g_es2[s] + g_ed2[d]));
    if (li == 0) atomicAdd(&g_den2[d], p);
    float4 hv = *(const float4*)&g_h2[s * 32 + li * 4];
    atomicAdd((float4*)&g_out2[d * 32 + li * 4],
              make_float4(hv.x * p, hv.y * p, hv.z * p, hv.w * p));
}

// ---------------- K6: init pools ----------------
__global__ void k_pool_init() {
    int i = blockIdx.x * blockDim.x + threadIdx.x;
    if (i < GG * 32) { g_msum[i] = 0.f; g_mmax[i] = 0u; }
    if (i < GG) g_cnt[i] = 0.f;
}

// ---------------- K7: finalize layer2 act, pools ----------------
__global__ void k_pool(const float* __restrict__ b2, const int* __restrict__ batch, int N) {
    int gid = blockIdx.x * blockDim.x + threadIdx.x;
    int n = gid >> 5, c = gid & 31;
    if (n >= N) return;
    float v = elu(g_out2[n * 32 + c] / (g_den2[n] + 1e-16f) + b2[c]);
    int g = batch[n];
    atomicAdd(&g_msum[g * 32 + c], v);
    atomicMax(&g_mmax[g * 32 + c], fenc(v));
    if (c == 0) atomicAdd(&g_cnt[g], 1.f);
}

// ---------------- K8: readout MLP ----------------
__global__ void k_mlp(const float* __restrict__ Wm1, const float* __restrict__ bm1,
                      const float* __restrict__ Wm2, const float* __restrict__ bm2,
                      float* __restrict__ out) {
    __shared__ float gv[64];
    __shared__ float red[64];
    int g = blockIdx.x, j = threadIdx.x;  // 64
    if (j < 32) gv[j] = g_msum[g * 32 + j] / g_cnt[g];
    else        gv[j] = fdec(g_mmax[g * 32 + (j - 32)]);
    __syncthreads();
    float acc = bm1[j];
    #pragma unroll 8
    for (int i = 0; i < 64; i++) acc += gv[i] * Wm1[i * 64 + j];
    red[j] = fmaxf(acc, 0.f) * Wm2[j];
    __syncthreads();
    for (int o = 32; o; o >>= 1) {
        if (j < o) red[j] += red[j + o];
        __syncthreads();
    }
    if (j == 0) out[g] = red[0] + bm2[0];
}

// ---------------- host ----------------
extern "C" void kernel_launch(void* const* d_in, const int* in_sizes, int n_in,
                              void* d_out, int out_size) {
    const float* x    = (const float*)d_in[0];
    const int*   ei   = (const int*)  d_in[1];
    const int*   bat  = (const int*)  d_in[2];
    const float* W1   = (const float*)d_in[3];
    const float* as1  = (const float*)d_in[4];
    const float* ad1  = (const float*)d_in[5];
    const float* b1   = (const float*)d_in[6];
    const float* W2   = (const float*)d_in[7];
    const float* as2  = (const float*)d_in[8];
    const float* ad2  = (const float*)d_in[9];
    const float* b2   = (const float*)d_in[10];
    const float* Wm1  = (const float*)d_in[11];
    const float* bm1  = (const float*)d_in[12];
    const float* Wm2  = (const float*)d_in[13];
    const float* bm2  = (const float*)d_in[14];
    float* out = (float*)d_out;

    int N = in_sizes[0] / 7;
    int E = in_sizes[1] / 2;
    const int* src = ei;
    const int* dst = ei + E;

    k_va<<<1, 32>>>(W1, as1, ad1);
    k_node1<<<(N + 255) / 256, 256>>>(x, N);
    {
        long long thr = (long long)E * 8;
        k_agg1<<<(int)((thr + 255) / 256), 256>>>(x, src, dst, E);
    }
    k_finish1<<<(N + 15) / 16, 128>>>(W1, b1, W2, as2, ad2, N);
    k_self2<<<(N * 32 + 255) / 256, 256>>>(N);
    {
        long long thr = (long long)E * 8;
        k_agg2<<<(int)((thr + 255) / 256), 256>>>(src, dst, E);
    }
    k_pool_init<<<(GG * 32 + 255) / 256, 256>>>();
    {
        long long thr = (long long)N * 32;
        k_pool<<<(int)((thr + 255) / 256), 256>>>(b2, bat, N);
    }
    k_mlp<<<GG, 64>>>(Wm1, bm1, Wm2, bm2, out);
}

// round 4
// speedup vs baseline: 2.7137x; 1.2694x over previous
#include <cuda_runtime.h>
#include <math.h>

#define NN 100000
#define EE 1700000
#define GG 1024

// ---------------- scratch ----------------
__device__ float    g_va_src[28];
__device__ float    g_va_dst[28];
__device__ float    g_es1 [NN * 4];
__device__ float    g_ed1 [NN * 4];
__device__ float    g_acc [NN * 32];    // per-dst: [h*7+i]=Σ p*x_i ; [28+h]=Σ p
__device__ float    g_h2  [NN * 32];
__device__ float    g_es2 [NN];
__device__ float    g_ed2 [NN];
__device__ float    g_den2[NN];
__device__ float    g_out2[NN * 32];
__device__ float    g_msum[GG * 32];
__device__ unsigned g_mmax[GG * 32];
__device__ float    g_cnt [GG];

// ---------------- helpers ----------------
__device__ __forceinline__ unsigned fenc(float f) {
    unsigned u = __float_as_uint(f);
    return (u & 0x80000000u) ? ~u : (u | 0x80000000u);
}
__device__ __forceinline__ float fdec(unsigned u) {
    return __uint_as_float((u & 0x80000000u) ? (u & 0x7FFFFFFFu) : ~u);
}
__device__ __forceinline__ float lrelu(float v) { return v > 0.f ? v : 0.2f * v; }
__device__ __forceinline__ float elu(float v)   { return v > 0.f ? v : expf(v) - 1.f; }

// ---------------- K0: va = W1 @ a (7x4 each) ----------------
__global__ void k_va(const float* __restrict__ W1, const float* __restrict__ as1,
                     const float* __restrict__ ad1) {
    int t = threadIdx.x;  // 32
    if (t < 28) {
        int i = t >> 2, h = t & 3;
        float ss = 0.f, dd = 0.f;
        #pragma unroll
        for (int c = 0; c < 32; c++) {
            float w = W1[i * 128 + h * 32 + c];
            ss += w * as1[h * 32 + c];
            dd += w * ad1[h * 32 + c];
        }
        g_va_src[i * 4 + h] = ss;
        g_va_dst[i * 4 + h] = dd;
    }
}

// ---------------- K1: per-node logits + self-loop-seeded accumulator ----------------
__global__ void k_node1(const float* __restrict__ x, int N) {
    int n = blockIdx.x * blockDim.x + threadIdx.x;
    if (n >= N) return;
    float xv[7];
    #pragma unroll
    for (int i = 0; i < 7; i++) xv[i] = x[n * 7 + i];
    float es[4], ed[4];
    #pragma unroll
    for (int h = 0; h < 4; h++) {
        float s = 0.f, d = 0.f;
        #pragma unroll
        for (int i = 0; i < 7; i++) {
            s += xv[i] * g_va_src[i * 4 + h];
            d += xv[i] * g_va_dst[i * 4 + h];
        }
        es[h] = s; ed[h] = d;
    }
    *(float4*)&g_es1[n * 4] = make_float4(es[0], es[1], es[2], es[3]);
    *(float4*)&g_ed1[n * 4] = make_float4(ed[0], ed[1], ed[2], ed[3]);
    float p[4];
    #pragma unroll
    for (int h = 0; h < 4; h++) p[h] = expf(lrelu(es[h] + ed[h]));
    float a[32];
    #pragma unroll
    for (int h = 0; h < 4; h++) {
        #pragma unroll
        for (int i = 0; i < 7; i++) a[h * 7 + i] = p[h] * xv[i];
        a[28 + h] = p[h];
    }
    #pragma unroll
    for (int q = 0; q < 8; q++)
        *(float4*)&g_acc[n * 32 + q * 4] = make_float4(a[q*4], a[q*4+1], a[q*4+2], a[q*4+3]);
}

// ---------------- K2: layer1 edge aggregation (8 lanes/edge, 32 floats) ----------------
__global__ void k_agg1(const float* __restrict__ x, const int* __restrict__ src,
                       const int* __restrict__ dst, int E) {
    int gid = blockIdx.x * blockDim.x + threadIdx.x;
    int e = gid >> 3, lane = gid & 7;
    if (e >= E) return;
    int s = src[e], d = dst[e];
    const float4 es = *(const float4*)&g_es1[s * 4];
    const float4 ed = *(const float4*)&g_ed1[d * 4];
    float p[4];
    p[0] = expf(lrelu(es.x + ed.x));
    p[1] = expf(lrelu(es.y + ed.y));
    p[2] = expf(lrelu(es.z + ed.z));
    p[3] = expf(lrelu(es.w + ed.w));
    const float* xs = &x[s * 7];
    float v[4];
    #pragma unroll
    for (int j = 0; j < 4; j++) {
        int idx = lane * 4 + j;
        int h7 = (idx * 9363) >> 16;        // idx/7 (exact for idx<32)
        int i7 = idx - h7 * 7;
        v[j] = (idx < 28) ? p[h7] * __ldg(&xs[i7]) : p[idx - 28];
    }
    atomicAdd((float4*)&g_acc[d * 32 + lane * 4], make_float4(v[0], v[1], v[2], v[3]));
}

// ---------------- K3: acc -> act1 -> h2 -> logits -> self2 seed (fused, tiled) ----------------
// 256 threads, 32 nodes/block. Warp w owns nodes [w*4, w*4+4). No per-node block syncs.
__global__ __launch_bounds__(256) void k_finish1(
        const float* __restrict__ W1, const float* __restrict__ b1,
        const float* __restrict__ W2, const float* __restrict__ as2,
        const float* __restrict__ ad2, int N) {
    __shared__ float sW1[896];
    __shared__ float sb1[128];
    __shared__ float sW2[4096];
    __shared__ float sas[32], sad[32];
    __shared__ float sacc[32][32];
    __shared__ float sact[32][128];
    int t = threadIdx.x;
    int w = t >> 5, lane = t & 31;
    for (int i = t; i < 896; i += 256) sW1[i] = W1[i];
    if (t < 128) sb1[t] = b1[t];
    for (int i = t; i < 4096; i += 256) sW2[i] = W2[i];
    if (t < 32) { sas[t] = as2[t]; sad[t] = ad2[t]; }

    int nbase = blockIdx.x * 32;
    // Stage A: load acc tile (coalesced)
    for (int i = t; i < 1024; i += 256) {
        int nl = i >> 5, c = i & 31;
        int n = nbase + nl;
        sacc[nl][c] = (n < N) ? g_acc[n * 32 + c] : 1.f;
    }
    __syncthreads();

    // Stage B: act1 for this warp's 4 nodes (broadcast sacc reads, coalesced sW1)
    #pragma unroll
    for (int j = 0; j < 4; j++) {
        int nl = w * 4 + j;
        #pragma unroll
        for (int q = 0; q < 4; q++) {
            float s = 0.f;
            #pragma unroll
            for (int i = 0; i < 7; i++)
                s += sacc[nl][q * 7 + i] * sW1[i * 128 + q * 32 + lane];
            float den = sacc[nl][28 + q] + 1e-16f;
            sact[nl][q * 32 + lane] = elu(s / den + sb1[q * 32 + lane]);
        }
    }
    __syncthreads();

    // Stage C: h2 = act1 @ W2 for 4 nodes; W2 value reused 4x; sact reads broadcast
    float h2a[4] = {0.f, 0.f, 0.f, 0.f};
    #pragma unroll 4
    for (int k = 0; k < 128; k++) {
        float wv = sW2[k * 32 + lane];
        #pragma unroll
        for (int j = 0; j < 4; j++) h2a[j] += sact[w * 4 + j][k] * wv;
    }

    // Epilogue: logits + fused layer2 self-loop seed
    #pragma unroll
    for (int j = 0; j < 4; j++) {
        int n = nbase + w * 4 + j;
        if (n >= N) continue;
        float h2 = h2a[j];
        float e_s = h2 * sas[lane], e_d = h2 * sad[lane];
        #pragma unroll
        for (int o = 16; o; o >>= 1) {
            e_s += __shfl_xor_sync(0xFFFFFFFFu, e_s, o);
            e_d += __shfl_xor_sync(0xFFFFFFFFu, e_d, o);
        }
        float p = expf(lrelu(e_s + e_d));
        g_h2[n * 32 + lane] = h2;
        g_out2[n * 32 + lane] = p * h2;
        if (lane == 0) { g_es2[n] = e_s; g_ed2[n] = e_d; g_den2[n] = p; }
    }
}

// ---------------- K5: layer2 edge aggregation (8 lanes/edge) ----------------
__global__ void k_agg2(const int* __restrict__ src, const int* __restrict__ dst, int E) {
    int gid = blockIdx.x * blockDim.x + threadIdx.x;
    int e = gid >> 3, li = gid & 7;
    if (e >= E) return;
    int s = src[e], d = dst[e];
    float p = expf(lrelu(g_es2[s] + g_ed2[d]));
    if (li == 0) atomicAdd(&g_den2[d], p);
    float4 hv = *(const float4*)&g_h2[s * 32 + li * 4];
    atomicAdd((float4*)&g_out2[d * 32 + li * 4],
              make_float4(hv.x * p, hv.y * p, hv.z * p, hv.w * p));
}

// ---------------- K6: init pools ----------------
__global__ void k_pool_init() {
    int i = blockIdx.x * blockDim.x + threadIdx.x;
    if (i < GG * 32) { g_msum[i] = 0.f; g_mmax[i] = 0u; }
    if (i < GG) g_cnt[i] = 0.f;
}

// ---------------- K7: finalize layer2 act, pools ----------------
__global__ void k_pool(const float* __restrict__ b2, const int* __restrict__ batch, int N) {
    int gid = blockIdx.x * blockDim.x + threadIdx.x;
    int n = gid >> 5, c = gid & 31;
    if (n >= N) return;
    float v = elu(g_out2[n * 32 + c] / (g_den2[n] + 1e-16f) + b2[c]);
    int g = batch[n];
    atomicAdd(&g_msum[g * 32 + c], v);
    atomicMax(&g_mmax[g * 32 + c], fenc(v));
    if (c == 0) atomicAdd(&g_cnt[g], 1.f);
}

// ---------------- K8: readout MLP ----------------
__global__ void k_mlp(const float* __restrict__ Wm1, const float* __restrict__ bm1,
                      const float* __restrict__ Wm2, const float* __restrict__ bm2,
                      float* __restrict__ out) {
    __shared__ float gv[64];
    __shared__ float red[64];
    int g = blockIdx.x, j = threadIdx.x;  // 64
    if (j < 32) gv[j] = g_msum[g * 32 + j] / g_cnt[g];
    else        gv[j] = fdec(g_mmax[g * 32 + (j - 32)]);
    __syncthreads();
    float acc = bm1[j];
    #pragma unroll 8
    for (int i = 0; i < 64; i++) acc += gv[i] * Wm1[i * 64 + j];
    red[j] = fmaxf(acc, 0.f) * Wm2[j];
    __syncthreads();
    for (int o = 32; o; o >>= 1) {
        if (j < o) red[j] += red[j + o];
        __syncthreads();
    }
    if (j == 0) out[g] = red[0] + bm2[0];
}

// ---------------- host ----------------
extern "C" void kernel_launch(void* const* d_in, const int* in_sizes, int n_in,
                              void* d_out, int out_size) {
    const float* x    = (const float*)d_in[0];
    const int*   ei   = (const int*)  d_in[1];
    const int*   bat  = (const int*)  d_in[2];
    const float* W1   = (const float*)d_in[3];
    const float* as1  = (const float*)d_in[4];
    const float* ad1  = (const float*)d_in[5];
    const float* b1   = (const float*)d_in[6];
    const float* W2   = (const float*)d_in[7];
    const float* as2  = (const float*)d_in[8];
    const float* ad2  = (const float*)d_in[9];
    const float* b2   = (const float*)d_in[10];
    const float* Wm1  = (const float*)d_in[11];
    const float* bm1  = (const float*)d_in[12];
    const float* Wm2  = (const float*)d_in[13];
    const float* bm2  = (const float*)d_in[14];
    float* out = (float*)d_out;

    int N = in_sizes[0] / 7;
    int E = in_sizes[1] / 2;
    const int* src = ei;
    const int* dst = ei + E;

    k_va<<<1, 32>>>(W1, as1, ad1);
    k_node1<<<(N + 255) / 256, 256>>>(x, N);
    {
        long long thr = (long long)E * 8;
        k_agg1<<<(int)((thr + 255) / 256), 256>>>(x, src, dst, E);
    }
    k_finish1<<<(N + 31) / 32, 256>>>(W1, b1, W2, as2, ad2, N);
    {
        long long thr = (long long)E * 8;
        k_agg2<<<(int)((thr + 255) / 256), 256>>>(src, dst, E);
    }
    k_pool_init<<<(GG * 32 + 255) / 256, 256>>>();
    {
        long long thr = (long long)N * 32;
        k_pool<<<(int)((thr + 255) / 256), 256>>>(b2, bat, N);
    }
    k_mlp<<<GG, 64>>>(Wm1, bm1, Wm2, bm2, out);
}

// round 5
// speedup vs baseline: 2.7269x; 1.0049x over previous
#include <cuda_runtime.h>
#include <math.h>

#define NN 100000
#define EE 1700000
#define GG 1024

// ---------------- scratch ----------------
__device__ float    g_va_src[28];
__device__ float    g_va_dst[28];
__device__ float    g_es1 [NN * 4];
__device__ float    g_ed1 [NN * 4];
__device__ float    g_acc [NN * 32];    // per-dst: [h*7+i]=Σ p*x_i ; [28+h]=Σ p
__device__ float    g_h2  [NN * 32];
__device__ float    g_es2 [NN];
__device__ float    g_ed2 [NN];
__device__ float    g_den2[NN];
__device__ float    g_out2[NN * 32];
__device__ float    g_msum[GG * 32];
__device__ unsigned g_mmax[GG * 32];
__device__ float    g_cnt [GG];

// ---------------- helpers ----------------
__device__ __forceinline__ unsigned fenc(float f) {
    unsigned u = __float_as_uint(f);
    return (u & 0x80000000u) ? ~u : (u | 0x80000000u);
}
__device__ __forceinline__ float fdec(unsigned u) {
    return __uint_as_float((u & 0x80000000u) ? (u & 0x7FFFFFFFu) : ~u);
}
__device__ __forceinline__ float lrelu(float v) { return v > 0.f ? v : 0.2f * v; }
__device__ __forceinline__ float elu(float v)   { return v > 0.f ? v : __expf(v) - 1.f; }

// ---------------- K0: va = W1 @ a (7x4 each) ----------------
__global__ void k_va(const float* __restrict__ W1, const float* __restrict__ as1,
                     const float* __restrict__ ad1) {
    int t = threadIdx.x;  // 32
    if (t < 28) {
        int i = t >> 2, h = t & 3;
        float ss = 0.f, dd = 0.f;
        #pragma unroll
        for (int c = 0; c < 32; c++) {
            float w = W1[i * 128 + h * 32 + c];
            ss += w * as1[h * 32 + c];
            dd += w * ad1[h * 32 + c];
        }
        g_va_src[i * 4 + h] = ss;
        g_va_dst[i * 4 + h] = dd;
    }
}

// ---------------- K1: per-node logits + self-loop-seeded accumulator ----------------
__global__ void k_node1(const float* __restrict__ x, int N) {
    int n = blockIdx.x * blockDim.x + threadIdx.x;
    if (n >= N) return;
    float xv[7];
    #pragma unroll
    for (int i = 0; i < 7; i++) xv[i] = x[n * 7 + i];
    float es[4], ed[4];
    #pragma unroll
    for (int h = 0; h < 4; h++) {
        float s = 0.f, d = 0.f;
        #pragma unroll
        for (int i = 0; i < 7; i++) {
            s += xv[i] * g_va_src[i * 4 + h];
            d += xv[i] * g_va_dst[i * 4 + h];
        }
        es[h] = s; ed[h] = d;
    }
    *(float4*)&g_es1[n * 4] = make_float4(es[0], es[1], es[2], es[3]);
    *(float4*)&g_ed1[n * 4] = make_float4(ed[0], ed[1], ed[2], ed[3]);
    float p[4];
    #pragma unroll
    for (int h = 0; h < 4; h++) p[h] = __expf(lrelu(es[h] + ed[h]));
    float a[32];
    #pragma unroll
    for (int h = 0; h < 4; h++) {
        #pragma unroll
        for (int i = 0; i < 7; i++) a[h * 7 + i] = p[h] * xv[i];
        a[28 + h] = p[h];
    }
    #pragma unroll
    for (int q = 0; q < 8; q++)
        *(float4*)&g_acc[n * 32 + q * 4] = make_float4(a[q*4], a[q*4+1], a[q*4+2], a[q*4+3]);
}

// ---------------- K2: layer1 edge aggregation (8 lanes/edge, 32 floats) ----------------
__global__ void k_agg1(const float* __restrict__ x, const int* __restrict__ src,
                       const int* __restrict__ dst, int E) {
    int gid = blockIdx.x * blockDim.x + threadIdx.x;
    int e = gid >> 3, lane = gid & 7;
    if (e >= E) return;
    int s = src[e], d = dst[e];
    const float4 es = *(const float4*)&g_es1[s * 4];
    const float4 ed = *(const float4*)&g_ed1[d * 4];
    float p[4];
    p[0] = __expf(lrelu(es.x + ed.x));
    p[1] = __expf(lrelu(es.y + ed.y));
    p[2] = __expf(lrelu(es.z + ed.z));
    p[3] = __expf(lrelu(es.w + ed.w));
    const float* xs = &x[s * 7];
    float v[4];
    #pragma unroll
    for (int j = 0; j < 4; j++) {
        int idx = lane * 4 + j;
        int h7 = (idx * 9363) >> 16;        // idx/7 (exact for idx<32)
        int i7 = idx - h7 * 7;
        v[j] = (idx < 28) ? p[h7] * __ldg(&xs[i7]) : p[idx - 28];
    }
    atomicAdd((float4*)&g_acc[d * 32 + lane * 4], make_float4(v[0], v[1], v[2], v[3]));
}

// ---------------- K3: acc -> act1 -> h2 -> logits -> self2 seed (fused, tiled) ----------------
// 256 threads, 32 nodes/block. Warp w owns nodes [w*4, w*4+4).
__global__ __launch_bounds__(256) void k_finish1(
        const float* __restrict__ W1, const float* __restrict__ b1,
        const float* __restrict__ W2, const float* __restrict__ as2,
        const float* __restrict__ ad2, int N) {
    __shared__ float sW1[896];
    __shared__ float sb1[128];
    __shared__ float sW2T[32][132];         // transposed, padded pitch (LDS.128 conflict-free)
    __shared__ float sas[32], sad[32];
    __shared__ float sacc[32][32];
    __shared__ float sact[32][128];
    int t = threadIdx.x;
    int w = t >> 5, lane = t & 31;
    for (int i = t; i < 896; i += 256) sW1[i] = W1[i];
    if (t < 128) sb1[t] = b1[t];
    for (int i = t; i < 4096; i += 256) {
        int k = i >> 5, c = i & 31;
        sW2T[c][k] = W2[i];
    }
    if (t < 32) { sas[t] = as2[t]; sad[t] = ad2[t]; }

    int nbase = blockIdx.x * 32;
    // Stage A: load acc tile (coalesced)
    for (int i = t; i < 1024; i += 256) {
        int nl = i >> 5, c = i & 31;
        int n = nbase + nl;
        sacc[nl][c] = (n < N) ? g_acc[n * 32 + c] : 1.f;
    }
    __syncthreads();

    // Stage B: act1 for this warp's 4 nodes
    #pragma unroll
    for (int j = 0; j < 4; j++) {
        int nl = w * 4 + j;
        #pragma unroll
        for (int q = 0; q < 4; q++) {
            float s = 0.f;
            #pragma unroll
            for (int i = 0; i < 7; i++)
                s += sacc[nl][q * 7 + i] * sW1[i * 128 + q * 32 + lane];
            float den = sacc[nl][28 + q] + 1e-16f;
            sact[nl][q * 32 + lane] = elu(__fdividef(s, den) + sb1[q * 32 + lane]);
        }
    }
    __syncthreads();

    // Stage C: h2 = act1 @ W2, vectorized LDS.128 on both operands
    float h2a[4] = {0.f, 0.f, 0.f, 0.f};
    #pragma unroll 4
    for (int q = 0; q < 32; q++) {
        float4 wv = *(const float4*)&sW2T[lane][q * 4];
        #pragma unroll
        for (int j = 0; j < 4; j++) {
            float4 av = *(const float4*)&sact[w * 4 + j][q * 4];
            h2a[j] += av.x * wv.x + av.y * wv.y + av.z * wv.z + av.w * wv.w;
        }
    }

    // Epilogue: logits + fused layer2 self-loop seed
    #pragma unroll
    for (int j = 0; j < 4; j++) {
        int n = nbase + w * 4 + j;
        if (n >= N) continue;
        float h2 = h2a[j];
        float e_s = h2 * sas[lane], e_d = h2 * sad[lane];
        #pragma unroll
        for (int o = 16; o; o >>= 1) {
            e_s += __shfl_xor_sync(0xFFFFFFFFu, e_s, o);
            e_d += __shfl_xor_sync(0xFFFFFFFFu, e_d, o);
        }
        float p = __expf(lrelu(e_s + e_d));
        g_h2[n * 32 + lane] = h2;
        g_out2[n * 32 + lane] = p * h2;
        if (lane == 0) { g_es2[n] = e_s; g_ed2[n] = e_d; g_den2[n] = p; }
    }
}

// ---------------- K5: layer2 edge aggregation (8 lanes/edge) ----------------
__global__ void k_agg2(const int* __restrict__ src, const int* __restrict__ dst, int E) {
    int gid = blockIdx.x * blockDim.x + threadIdx.x;
    int e = gid >> 3, li = gid & 7;
    if (e >= E) return;
    int s = src[e], d = dst[e];
    float p = __expf(lrelu(g_es2[s] + g_ed2[d]));
    if (li == 0) atomicAdd(&g_den2[d], p);
    float4 hv = *(const float4*)&g_h2[s * 32 + li * 4];
    atomicAdd((float4*)&g_out2[d * 32 + li * 4],
              make_float4(hv.x * p, hv.y * p, hv.z * p, hv.w * p));
}

// ---------------- K6: init pools ----------------
__global__ void k_pool_init() {
    int i = blockIdx.x * blockDim.x + threadIdx.x;
    if (i < GG * 32) { g_msum[i] = 0.f; g_mmax[i] = 0u; }
    if (i < GG) g_cnt[i] = 0.f;
}

// ---------------- K7: finalize layer2 act, pools ----------------
__global__ void k_pool(const float* __restrict__ b2, const int* __restrict__ batch, int N) {
    int gid = blockIdx.x * blockDim.x + threadIdx.x;
    int n = gid >> 5, c = gid & 31;
    if (n >= N) return;
    float v = elu(__fdividef(g_out2[n * 32 + c], g_den2[n] + 1e-16f) + b2[c]);
    int g = batch[n];
    atomicAdd(&g_msum[g * 32 + c], v);
    atomicMax(&g_mmax[g * 32 + c], fenc(v));
    if (c == 0) atomicAdd(&g_cnt[g], 1.f);
}

// ---------------- K8: readout MLP ----------------
__global__ void k_mlp(const float* __restrict__ Wm1, const float* __restrict__ bm1,
                      const float* __restrict__ Wm2, const float* __restrict__ bm2,
                      float* __restrict__ out) {
    __shared__ float gv[64];
    __shared__ float red[64];
    int g = blockIdx.x, j = threadIdx.x;  // 64
    if (j < 32) gv[j] = g_msum[g * 32 + j] / g_cnt[g];
    else        gv[j] = fdec(g_mmax[g * 32 + (j - 32)]);
    __syncthreads();
    float acc = bm1[j];
    #pragma unroll 8
    for (int i = 0; i < 64; i++) acc += gv[i] * Wm1[i * 64 + j];
    red[j] = fmaxf(acc, 0.f) * Wm2[j];
    __syncthreads();
    for (int o = 32; o; o >>= 1) {
        if (j < o) red[j] += red[j + o];
        __syncthreads();
    }
    if (j == 0) out[g] = red[0] + bm2[0];
}

// ---------------- host ----------------
extern "C" void kernel_launch(void* const* d_in, const int* in_sizes, int n_in,
                              void* d_out, int out_size) {
    const float* x    = (const float*)d_in[0];
    const int*   ei   = (const int*)  d_in[1];
    const int*   bat  = (const int*)  d_in[2];
    const float* W1   = (const float*)d_in[3];
    const float* as1  = (const float*)d_in[4];
    const float* ad1  = (const float*)d_in[5];
    const float* b1   = (const float*)d_in[6];
    const float* W2   = (const float*)d_in[7];
    const float* as2  = (const float*)d_in[8];
    const float* ad2  = (const float*)d_in[9];
    const float* b2   = (const float*)d_in[10];
    const float* Wm1  = (const float*)d_in[11];
    const float* bm1  = (const float*)d_in[12];
    const float* Wm2  = (const float*)d_in[13];
    const float* bm2  = (const float*)d_in[14];
    float* out = (float*)d_out;

    int N = in_sizes[0] / 7;
    int E = in_sizes[1] / 2;
    const int* src = ei;
    const int* dst = ei + E;

    k_va<<<1, 32>>>(W1, as1, ad1);
    k_node1<<<(N + 255) / 256, 256>>>(x, N);
    {
        long long thr = (long long)E * 8;
        k_agg1<<<(int)((thr + 255) / 256), 256>>>(x, src, dst, E);
    }
    k_finish1<<<(N + 31) / 32, 256>>>(W1, b1, W2, as2, ad2, N);
    {
        long long thr = (long long)E * 8;
        k_agg2<<<(int)((thr + 255) / 256), 256>>>(src, dst, E);
    }
    k_pool_init<<<(GG * 32 + 255) / 256, 256>>>();
    {
        long long thr = (long long)N * 32;
        k_pool<<<(int)((thr + 255) / 256), 256>>>(b2, bat, N);
    }
    k_mlp<<<GG, 64>>>(Wm1, bm1, Wm2, bm2, out);
}

// round 6
// speedup vs baseline: 3.1803x; 1.1662x over previous
#include <cuda_runtime.h>
#include <math.h>

#define NN 100000
#define EE 1700000
#define GG 1024

// ---------------- scratch ----------------
__device__ float    g_va_src[28];
__device__ float    g_va_dst[28];
__device__ float    g_es1 [NN * 4];
__device__ float    g_ed1 [NN * 4];
__device__ float    g_acc [NN * 32];    // per-dst: [h*7+i]=Σ p*x_i ; [28+h]=Σ p
__device__ float    g_h2  [NN * 32];
__device__ float    g_es2 [NN];
__device__ float    g_ed2 [NN];
__device__ float    g_den2[NN];
__device__ float    g_out2[NN * 32];
__device__ float    g_msum[GG * 32];
__device__ unsigned g_mmax[GG * 32];
__device__ float    g_cnt [GG];

// ---------------- helpers ----------------
__device__ __forceinline__ unsigned fenc(float f) {
    unsigned u = __float_as_uint(f);
    return (u & 0x80000000u) ? ~u : (u | 0x80000000u);
}
__device__ __forceinline__ float fdec(unsigned u) {
    return __uint_as_float((u & 0x80000000u) ? (u & 0x7FFFFFFFu) : ~u);
}
__device__ __forceinline__ float lrelu(float v) { return v > 0.f ? v : 0.2f * v; }
__device__ __forceinline__ float elu(float v)   { return v > 0.f ? v : __expf(v) - 1.f; }

// ---------------- K0: va = W1 @ a (7x4 each) ----------------
__global__ void k_va(const float* __restrict__ W1, const float* __restrict__ as1,
                     const float* __restrict__ ad1) {
    int t = threadIdx.x;  // 32
    if (t < 28) {
        int i = t >> 2, h = t & 3;
        float ss = 0.f, dd = 0.f;
        #pragma unroll
        for (int c = 0; c < 32; c++) {
            float w = W1[i * 128 + h * 32 + c];
            ss += w * as1[h * 32 + c];
            dd += w * ad1[h * 32 + c];
        }
        g_va_src[i * 4 + h] = ss;
        g_va_dst[i * 4 + h] = dd;
    }
}

// ---------------- K1: per-node logits + self-loop-seeded accumulator ----------------
__global__ void k_node1(const float* __restrict__ x, int N) {
    int n = blockIdx.x * blockDim.x + threadIdx.x;
    if (n >= N) return;
    float xv[7];
    #pragma unroll
    for (int i = 0; i < 7; i++) xv[i] = x[n * 7 + i];
    float es[4], ed[4];
    #pragma unroll
    for (int h = 0; h < 4; h++) {
        float s = 0.f, d = 0.f;
        #pragma unroll
        for (int i = 0; i < 7; i++) {
            s += xv[i] * g_va_src[i * 4 + h];
            d += xv[i] * g_va_dst[i * 4 + h];
        }
        es[h] = s; ed[h] = d;
    }
    *(float4*)&g_es1[n * 4] = make_float4(es[0], es[1], es[2], es[3]);
    *(float4*)&g_ed1[n * 4] = make_float4(ed[0], ed[1], ed[2], ed[3]);
    float p[4];
    #pragma unroll
    for (int h = 0; h < 4; h++) p[h] = __expf(lrelu(es[h] + ed[h]));
    float a[32];
    #pragma unroll
    for (int h = 0; h < 4; h++) {
        #pragma unroll
        for (int i = 0; i < 7; i++) a[h * 7 + i] = p[h] * xv[i];
        a[28 + h] = p[h];
    }
    #pragma unroll
    for (int q = 0; q < 8; q++)
        *(float4*)&g_acc[n * 32 + q * 4] = make_float4(a[q*4], a[q*4+1], a[q*4+2], a[q*4+3]);
}

// ---------------- K2: layer1 edge aggregation, two-phase ----------------
// Phase 1: thread-per-edge computes p[4] (MUFU fully packed). Phase 2: 8 lanes/edge atomics.
__global__ __launch_bounds__(256) void k_agg1(
        const float* __restrict__ x, const int* __restrict__ src,
        const int* __restrict__ dst, int E) {
    __shared__ float sp[256 * 4];
    __shared__ int   ssrc[256];
    __shared__ int   sdst[256];
    int t = threadIdx.x;
    int ebase = blockIdx.x << 8;
    int e = ebase + t;
    if (e < E) {
        int s = src[e], d = dst[e];
        const float4 es = *(const float4*)&g_es1[s * 4];
        const float4 ed = *(const float4*)&g_ed1[d * 4];
        sp[t * 4 + 0] = __expf(lrelu(es.x + ed.x));
        sp[t * 4 + 1] = __expf(lrelu(es.y + ed.y));
        sp[t * 4 + 2] = __expf(lrelu(es.z + ed.z));
        sp[t * 4 + 3] = __expf(lrelu(es.w + ed.w));
        ssrc[t] = s; sdst[t] = d;
    }
    __syncthreads();
    int lane = t & 7, eg = t >> 3;       // 32 groups of 8 lanes
    int eend = min(256, E - ebase);
    #pragma unroll 2
    for (int r = 0; r < 8; r++) {
        int le = eg * 8 + r;             // group eg covers edges [eg*8, eg*8+8)
        if (le >= eend) break;
        int s = ssrc[le], d = sdst[le];
        float p[4] = { sp[le*4], sp[le*4+1], sp[le*4+2], sp[le*4+3] };
        const float* xs = &x[s * 7];
        float v[4];
        #pragma unroll
        for (int j = 0; j < 4; j++) {
            int idx = lane * 4 + j;
            int h7 = (idx * 9363) >> 16;  // idx/7 (exact for idx<32)
            int i7 = idx - h7 * 7;
            v[j] = (idx < 28) ? p[h7] * __ldg(&xs[i7]) : p[idx - 28];
        }
        atomicAdd((float4*)&g_acc[d * 32 + lane * 4], make_float4(v[0], v[1], v[2], v[3]));
    }
}

// ---------------- K3: acc -> act1 -> h2 -> logits -> self2 seed (fused) ----------------
// 256 threads, 32 nodes/block, warp owns 4 nodes. W2 read from global (L1-resident).
__global__ __launch_bounds__(256, 6) void k_finish1(
        const float* __restrict__ W1, const float* __restrict__ b1,
        const float* __restrict__ W2, const float* __restrict__ as2,
        const float* __restrict__ ad2, int N) {
    __shared__ float sW1[896];
    __shared__ float sb1[128];
    __shared__ float sas[32], sad[32];
    __shared__ float sacc[32][32];
    __shared__ float sact[32][128];
    int t = threadIdx.x;
    int w = t >> 5, lane = t & 31;
    for (int i = t; i < 896; i += 256) sW1[i] = W1[i];
    if (t < 128) sb1[t] = b1[t];
    if (t < 32) { sas[t] = as2[t]; sad[t] = ad2[t]; }

    int nbase = blockIdx.x * 32;
    for (int i = t; i < 1024; i += 256) {
        int nl = i >> 5, c = i & 31;
        int n = nbase + nl;
        sacc[nl][c] = (n < N) ? g_acc[n * 32 + c] : 1.f;
    }
    __syncthreads();

    // Stage B: act1 for this warp's 4 nodes
    #pragma unroll
    for (int j = 0; j < 4; j++) {
        int nl = w * 4 + j;
        #pragma unroll
        for (int q = 0; q < 4; q++) {
            float s = 0.f;
            #pragma unroll
            for (int i = 0; i < 7; i++)
                s += sacc[nl][q * 7 + i] * sW1[i * 128 + q * 32 + lane];
            float den = sacc[nl][28 + q] + 1e-16f;
            sact[nl][q * 32 + lane] = elu(__fdividef(s, den) + sb1[q * 32 + lane]);
        }
    }
    __syncwarp();   // warp reads only its own sact rows below

    // Stage C: h2 = act1 @ W2; W2 from global (coalesced, L1-hot), sact broadcast
    float h2a[4] = {0.f, 0.f, 0.f, 0.f};
    #pragma unroll 4
    for (int k = 0; k < 128; k++) {
        float wv = __ldg(&W2[k * 32 + lane]);
        #pragma unroll
        for (int j = 0; j < 4; j++) h2a[j] += sact[w * 4 + j][k] * wv;
    }

    // Epilogue: logits + fused layer2 self-loop seed
    #pragma unroll
    for (int j = 0; j < 4; j++) {
        int n = nbase + w * 4 + j;
        if (n >= N) continue;
        float h2 = h2a[j];
        float e_s = h2 * sas[lane], e_d = h2 * sad[lane];
        #pragma unroll
        for (int o = 16; o; o >>= 1) {
            e_s += __shfl_xor_sync(0xFFFFFFFFu, e_s, o);
            e_d += __shfl_xor_sync(0xFFFFFFFFu, e_d, o);
        }
        float p = __expf(lrelu(e_s + e_d));
        g_h2[n * 32 + lane] = h2;
        g_out2[n * 32 + lane] = p * h2;
        if (lane == 0) { g_es2[n] = e_s; g_ed2[n] = e_d; g_den2[n] = p; }
    }
}

// ---------------- K5: layer2 edge aggregation, two-phase ----------------
__global__ __launch_bounds__(256) void k_agg2(
        const int* __restrict__ src, const int* __restrict__ dst, int E) {
    __shared__ float sp[256];
    __shared__ int   ssrc[256];
    __shared__ int   sdst[256];
    int t = threadIdx.x;
    int ebase = blockIdx.x << 8;
    int e = ebase + t;
    if (e < E) {
        int s = src[e], d = dst[e];
        float p = __expf(lrelu(g_es2[s] + g_ed2[d]));
        atomicAdd(&g_den2[d], p);
        sp[t] = p; ssrc[t] = s; sdst[t] = d;
    }
    __syncthreads();
    int lane = t & 7, eg = t >> 3;
    int eend = min(256, E - ebase);
    #pragma unroll 2
    for (int r = 0; r < 8; r++) {
        int le = eg * 8 + r;
        if (le >= eend) break;
        int s = ssrc[le], d = sdst[le];
        float p = sp[le];
        float4 hv = *(const float4*)&g_h2[s * 32 + lane * 4];
        atomicAdd((float4*)&g_out2[d * 32 + lane * 4],
                  make_float4(hv.x * p, hv.y * p, hv.z * p, hv.w * p));
    }
}

// ---------------- K6: init pools ----------------
__global__ void k_pool_init() {
    int i = blockIdx.x * blockDim.x + threadIdx.x;
    if (i < GG * 32) { g_msum[i] = 0.f; g_mmax[i] = 0u; }
    if (i < GG) g_cnt[i] = 0.f;
}

// ---------------- K7: finalize layer2 act, pools ----------------
__global__ void k_pool(const float* __restrict__ b2, const int* __restrict__ batch, int N) {
    int gid = blockIdx.x * blockDim.x + threadIdx.x;
    int n = gid >> 5, c = gid & 31;
    if (n >= N) return;
    float v = elu(__fdividef(g_out2[n * 32 + c], g_den2[n] + 1e-16f) + b2[c]);
    int g = batch[n];
    atomicAdd(&g_msum[g * 32 + c], v);
    atomicMax(&g_mmax[g * 32 + c], fenc(v));
    if (c == 0) atomicAdd(&g_cnt[g], 1.f);
}

// ---------------- K8: readout MLP ----------------
__global__ void k_mlp(const float* __restrict__ Wm1, const float* __restrict__ bm1,
                      const float* __restrict__ Wm2, const float* __restrict__ bm2,
                      float* __restrict__ out) {
    __shared__ float gv[64];
    __shared__ float red[64];
    int g = blockIdx.x, j = threadIdx.x;  // 64
    if (j < 32) gv[j] = g_msum[g * 32 + j] / g_cnt[g];
    else        gv[j] = fdec(g_mmax[g * 32 + (j - 32)]);
    __syncthreads();
    float acc = bm1[j];
    #pragma unroll 8
    for (int i = 0; i < 64; i++) acc += gv[i] * Wm1[i * 64 + j];
    red[j] = fmaxf(acc, 0.f) * Wm2[j];
    __syncthreads();
    for (int o = 32; o; o >>= 1) {
        if (j < o) red[j] += red[j + o];
        __syncthreads();
    }
    if (j == 0) out[g] = red[0] + bm2[0];
}

// ---------------- host ----------------
extern "C" void kernel_launch(void* const* d_in, const int* in_sizes, int n_in,
                              void* d_out, int out_size) {
    const float* x    = (const float*)d_in[0];
    const int*   ei   = (const int*)  d_in[1];
    const int*   bat  = (const int*)  d_in[2];
    const float* W1   = (const float*)d_in[3];
    const float* as1  = (const float*)d_in[4];
    const float* ad1  = (const float*)d_in[5];
    const float* b1   = (const float*)d_in[6];
    const float* W2   = (const float*)d_in[7];
    const float* as2  = (const float*)d_in[8];
    const float* ad2  = (const float*)d_in[9];
    const float* b2   = (const float*)d_in[10];
    const float* Wm1  = (const float*)d_in[11];
    const float* bm1  = (const float*)d_in[12];
    const float* Wm2  = (const float*)d_in[13];
    const float* bm2  = (const float*)d_in[14];
    float* out = (float*)d_out;

    int N = in_sizes[0] / 7;
    int E = in_sizes[1] / 2;
    const int* src = ei;
    const int* dst = ei + E;

    k_va<<<1, 32>>>(W1, as1, ad1);
    k_node1<<<(N + 255) / 256, 256>>>(x, N);
    k_agg1<<<(E + 255) / 256, 256>>>(x, src, dst, E);
    k_finish1<<<(N + 31) / 32, 256>>>(W1, b1, W2, as2, ad2, N);
    k_agg2<<<(E + 255) / 256, 256>>>(src, dst, E);
    k_pool_init<<<(GG * 32 + 255) / 256, 256>>>();
    {
        long long thr = (long long)N * 32;
        k_pool<<<(int)((thr + 255) / 256), 256>>>(b2, bat, N);
    }
    k_mlp<<<GG, 64>>>(Wm1, bm1, Wm2, bm2, out);
}